// round 4
// baseline (speedup 1.0000x reference)
#include <cuda_runtime.h>

#define B  16
#define TE 128
#define TD 128
#define H  256

// Scratch (no allocation allowed -> __device__ globals)
__device__ float g_ortho[B*TE*H];
__device__ float g_was[B*TE*H];
__device__ float g_uah[B*TD*H];

__device__ __forceinline__ float tanh_fast(float x) {
    float y;
    asm("tanh.approx.f32 %0, %1;" : "=f"(y) : "f"(x));
    return y;
}

// ---------------------------------------------------------------------------
// Kernel 1: orthogonalize encoder.
// For each (b,h): s_i = sum_{j<i} x_j ; out = x - ((x*s)/(x*x))*x  (elementwise)
// grid: 32 blocks x 128 threads; thread <-> (b, h) chain of length TE.
// Unroll-by-8 load batches for MLP.
// ---------------------------------------------------------------------------
__global__ void ortho_kernel(const float* __restrict__ enc) {
    int b = blockIdx.x >> 1;
    int h = ((blockIdx.x & 1) << 7) + threadIdx.x;   // 0..255
    const float* p = enc     + (size_t)(b*TE)*H + h;
    float*       q = g_ortho + (size_t)(b*TE)*H + h;
    float s = 0.f;
    float xv[8];
    for (int i0 = 0; i0 < TE; i0 += 8) {
        #pragma unroll
        for (int u = 0; u < 8; u++) xv[u] = p[(i0+u)*H];
        #pragma unroll
        for (int u = 0; u < 8; u++) {
            float x = xv[u];
            float r = (x*s)/(x*x);
            q[(i0+u)*H] = x - r*x;
            s += x;
        }
    }
}

// ---------------------------------------------------------------------------
// Kernel 2/3: C[M=2048,256] = A[M,256] @ W[256,256]
// 64x64 block tile, 256 threads, 4x4 micro-tile, K-chunk 16.
// MODE 0: A = g_ortho, C = g_was (encoder path)
// MODE 1: A = A_ext,   C = g_uah (decoder path)
// ---------------------------------------------------------------------------
template<int MODE>
__global__ void gemm256(const float* __restrict__ A_ext,
                        const float* __restrict__ W) {
    __shared__ float As[16][64];   // As[k][m]
    __shared__ float Ws[16][64];   // Ws[k][n]
    const float* A = (MODE == 0) ? g_ortho : A_ext;
    float*       C = (MODE == 0) ? g_was   : g_uah;

    int tid = threadIdx.x;
    int m0 = blockIdx.x * 64;
    int n0 = blockIdx.y * 64;
    int tx = tid & 15, ty = tid >> 4;

    int lm  = tid >> 2;         // 0..63 row for A load
    int lk4 = (tid & 3) * 4;    // k offset 0,4,8,12
    int wk  = tid >> 6;         // 0..3
    int wn  = tid & 63;

    float acc[4][4];
    #pragma unroll
    for (int i = 0; i < 4; i++)
        #pragma unroll
        for (int j = 0; j < 4; j++) acc[i][j] = 0.f;

    for (int kc = 0; kc < 256; kc += 16) {
        float4 a = *reinterpret_cast<const float4*>(&A[(size_t)(m0+lm)*256 + kc + lk4]);
        As[lk4+0][lm] = a.x; As[lk4+1][lm] = a.y;
        As[lk4+2][lm] = a.z; As[lk4+3][lm] = a.w;
        #pragma unroll
        for (int r = 0; r < 4; r++)
            Ws[wk + r*4][wn] = W[(size_t)(kc + wk + r*4)*256 + n0 + wn];
        __syncthreads();
        #pragma unroll
        for (int k = 0; k < 16; k++) {
            float4 av = *reinterpret_cast<const float4*>(&As[k][ty*4]);
            float4 wv = *reinterpret_cast<const float4*>(&Ws[k][tx*4]);
            float aa[4] = {av.x, av.y, av.z, av.w};
            float ww[4] = {wv.x, wv.y, wv.z, wv.w};
            #pragma unroll
            for (int i = 0; i < 4; i++)
                #pragma unroll
                for (int j = 0; j < 4; j++)
                    acc[i][j] += aa[i]*ww[j];
        }
        __syncthreads();
    }
    #pragma unroll
    for (int i = 0; i < 4; i++) {
        float4 o; o.x = acc[i][0]; o.y = acc[i][1]; o.z = acc[i][2]; o.w = acc[i][3];
        *reinterpret_cast<float4*>(&C[(size_t)(m0+ty*4+i)*256 + n0 + tx*4]) = o;
    }
}

// ---------------------------------------------------------------------------
// Kernel 4: energy + softmax + context, per (b, 4-d tile).
// energy[b,d,e] = sum_h tanh(was[b,e,h] + uah[b,d,h]) * V[h]
// p = softmax_e(energy);  c[b,d,h] = sum_e p * ortho[b,e,h]
// block: 256 threads (8 warps). warp handles one e per pass (16 passes),
// accumulating 4 d's at once (amortizes the was[b,e,:] read 4x).
// ---------------------------------------------------------------------------
__global__ void attn_kernel(const float* __restrict__ Va,
                            float* __restrict__ c_out,
                            float* __restrict__ e_out) {
    __shared__ float u_sm[4][H];
    __shared__ float V_sm[H];
    __shared__ float en_sm[4][TE];

    int b  = blockIdx.x >> 5;
    int d0 = (blockIdx.x & 31) * 4;
    int tid = threadIdx.x;

    for (int l = tid; l < 4*H; l += 256) {
        int d = l >> 8, h = l & 255;
        u_sm[d][h] = g_uah[(size_t)((b*TD + d0 + d))*H + h];
    }
    V_sm[tid] = Va[tid];
    __syncthreads();

    int warp = tid >> 5, lane = tid & 31;

    // ---- energies ----
    for (int pass = 0; pass < 16; pass++) {
        int e = pass*8 + warp;
        const float* wrow = g_was + (size_t)(b*TE + e)*H;
        float a0 = 0.f, a1 = 0.f, a2 = 0.f, a3 = 0.f;
        #pragma unroll
        for (int j = 0; j < 8; j++) {
            int h = lane + 32*j;
            float w = wrow[h];
            float v = V_sm[h];
            a0 += tanh_fast(w + u_sm[0][h]) * v;
            a1 += tanh_fast(w + u_sm[1][h]) * v;
            a2 += tanh_fast(w + u_sm[2][h]) * v;
            a3 += tanh_fast(w + u_sm[3][h]) * v;
        }
        #pragma unroll
        for (int off = 16; off; off >>= 1) {
            a0 += __shfl_xor_sync(0xffffffffu, a0, off);
            a1 += __shfl_xor_sync(0xffffffffu, a1, off);
            a2 += __shfl_xor_sync(0xffffffffu, a2, off);
            a3 += __shfl_xor_sync(0xffffffffu, a3, off);
        }
        if (lane == 0) {
            en_sm[0][e] = a0; en_sm[1][e] = a1;
            en_sm[2][e] = a2; en_sm[3][e] = a3;
        }
    }
    __syncthreads();

    // ---- softmax over e (warp d handles row d) ----
    if (warp < 4) {
        int d = warp;
        float v0 = en_sm[d][lane],     v1 = en_sm[d][lane+32];
        float v2 = en_sm[d][lane+64],  v3 = en_sm[d][lane+96];
        float m = fmaxf(fmaxf(v0, v1), fmaxf(v2, v3));
        #pragma unroll
        for (int off = 16; off; off >>= 1)
            m = fmaxf(m, __shfl_xor_sync(0xffffffffu, m, off));
        v0 = __expf(v0 - m); v1 = __expf(v1 - m);
        v2 = __expf(v2 - m); v3 = __expf(v3 - m);
        float s = v0 + v1 + v2 + v3;
        #pragma unroll
        for (int off = 16; off; off >>= 1)
            s += __shfl_xor_sync(0xffffffffu, s, off);
        float inv = 1.0f / s;
        v0 *= inv; v1 *= inv; v2 *= inv; v3 *= inv;
        en_sm[d][lane]    = v0; en_sm[d][lane+32] = v1;
        en_sm[d][lane+64] = v2; en_sm[d][lane+96] = v3;
        float* er = e_out + (size_t)(b*TD + d0 + d)*TE;
        er[lane]    = v0; er[lane+32] = v1;
        er[lane+64] = v2; er[lane+96] = v3;
    }
    __syncthreads();

    // ---- context: c[d][h] = sum_e p[d][e] * ortho[b,e,h] ----
    int h = tid;
    const float* orow = g_ortho + (size_t)(b*TE)*H + h;
    float c0 = 0.f, c1 = 0.f, c2 = 0.f, c3 = 0.f;
    #pragma unroll 4
    for (int e = 0; e < TE; e++) {
        float x = orow[e*H];
        c0 += en_sm[0][e]*x; c1 += en_sm[1][e]*x;
        c2 += en_sm[2][e]*x; c3 += en_sm[3][e]*x;
    }
    c_out[(size_t)(b*TD + d0 + 0)*H + h] = c0;
    c_out[(size_t)(b*TD + d0 + 1)*H + h] = c1;
    c_out[(size_t)(b*TD + d0 + 2)*H + h] = c2;
    c_out[(size_t)(b*TD + d0 + 3)*H + h] = c3;
}

// ---------------------------------------------------------------------------
extern "C" void kernel_launch(void* const* d_in, const int* in_sizes, int n_in,
                              void* d_out, int out_size) {
    const float* enc = (const float*)d_in[0];
    const float* dec = (const float*)d_in[1];
    const float* Wa  = (const float*)d_in[2];
    const float* Ua  = (const float*)d_in[3];
    const float* Va  = (const float*)d_in[4];

    float* out   = (float*)d_out;
    float* c_out = out;                    // [B, TD, H]
    float* e_out = out + (size_t)B*TD*H;   // [B, TD, TE]

    ortho_kernel<<<32, 128>>>(enc);
    gemm256<0><<<dim3(32, 4), 256>>>(nullptr, Wa);   // was = ortho @ W_a
    gemm256<1><<<dim3(32, 4), 256>>>(dec, Ua);       // uah = dec   @ U_a
    attn_kernel<<<B * (TD/4), 256>>>(Va, c_out, e_out);
}

// round 5
// speedup vs baseline: 1.2069x; 1.2069x over previous
#include <cuda_runtime.h>

#define B  16
#define TE 128
#define TD 128
#define H  256

typedef unsigned long long ull;

// Scratch (no allocation allowed -> __device__ globals)
__device__ float g_ortho[B*TE*H];
__device__ float g_was[B*TE*H];
__device__ float g_uah[B*TD*H];

__device__ __forceinline__ float tanh_fast(float x) {
    float y;
    asm("tanh.approx.f32 %0, %1;" : "=f"(y) : "f"(x));
    return y;
}
__device__ __forceinline__ ull pack2(float lo, float hi) {
    ull r; asm("mov.b64 %0, {%1, %2};" : "=l"(r) : "f"(lo), "f"(hi)); return r;
}
__device__ __forceinline__ void unpack2(ull v, float& lo, float& hi) {
    asm("mov.b64 {%0, %1}, %2;" : "=f"(lo), "=f"(hi) : "l"(v));
}
// packed fp32x2 FMA (Blackwell FFMA2): d = a*b + d
__device__ __forceinline__ void fma2(ull& d, ull a, ull b) {
    asm("fma.rn.f32x2 %0, %1, %2, %0;" : "+l"(d) : "l"(a), "l"(b));
}

// ---------------------------------------------------------------------------
// Kernel 1: orthogonalize encoder.
// For each (b,h): s_i = sum_{j<i} x_j ; out = x - ((x*s)/(x*x))*x (elementwise)
// 32 blocks x 128 threads; thread <-> (b,h) chain of length TE.
// Batch-32 loads (32 LDG in flight) to cover DRAM latency.
// ---------------------------------------------------------------------------
__global__ void ortho_kernel(const float* __restrict__ enc) {
    int b = blockIdx.x >> 1;
    int h = ((blockIdx.x & 1) << 7) + threadIdx.x;   // 0..255
    const float* p = enc     + (size_t)(b*TE)*H + h;
    float*       q = g_ortho + (size_t)(b*TE)*H + h;
    float s = 0.f;
    float x[32];
    #pragma unroll
    for (int u = 0; u < 32; u++) x[u] = p[u*H];
    #pragma unroll 1
    for (int i0 = 0; i0 < TE; i0 += 32) {
        float nx[32];
        if (i0 + 32 < TE) {
            #pragma unroll
            for (int u = 0; u < 32; u++) nx[u] = p[(i0+32+u)*H];
        }
        #pragma unroll
        for (int u = 0; u < 32; u++) {
            float xv = x[u];
            float r = __fdividef(xv*s, xv*xv);
            q[(i0+u)*H] = xv - r*xv;
            s += xv;
        }
        if (i0 + 32 < TE) {
            #pragma unroll
            for (int u = 0; u < 32; u++) x[u] = nx[u];
        }
    }
}

// ---------------------------------------------------------------------------
// Kernel 2: both GEMMs in one launch. C[2048,256] = A[2048,256] @ W[256,256]
// blockIdx.z: 0 -> was = ortho @ W_a ; 1 -> uah = dec @ U_a
// 64x64 tile, 256 threads, 4x4 micro-tile done as 4x2 packed f32x2.
// ---------------------------------------------------------------------------
__global__ void gemm_both(const float* __restrict__ dec,
                          const float* __restrict__ Wa,
                          const float* __restrict__ Ua) {
    __shared__ float As[16][64];   // As[k][m]
    __shared__ float Ws[16][64];   // Ws[k][n]
    int mode = blockIdx.z;
    const float* A = (mode == 0) ? g_ortho : dec;
    const float* W = (mode == 0) ? Wa      : Ua;
    float*       C = (mode == 0) ? g_was   : g_uah;

    int tid = threadIdx.x;
    int m0 = blockIdx.x * 64;
    int n0 = blockIdx.y * 64;
    int tx = tid & 15, ty = tid >> 4;

    int lm  = tid >> 2;         // 0..63 row for A load
    int lk4 = (tid & 3) * 4;    // k offset 0,4,8,12
    int wk  = tid >> 6;         // 0..3
    int wn  = tid & 63;

    ull acc[4][2];
    #pragma unroll
    for (int i = 0; i < 4; i++) { acc[i][0] = 0ull; acc[i][1] = 0ull; }

    for (int kc = 0; kc < 256; kc += 16) {
        float4 a = *reinterpret_cast<const float4*>(&A[(size_t)(m0+lm)*256 + kc + lk4]);
        As[lk4+0][lm] = a.x; As[lk4+1][lm] = a.y;
        As[lk4+2][lm] = a.z; As[lk4+3][lm] = a.w;
        #pragma unroll
        for (int r = 0; r < 4; r++)
            Ws[wk + r*4][wn] = W[(size_t)(kc + wk + r*4)*256 + n0 + wn];
        __syncthreads();
        #pragma unroll
        for (int k = 0; k < 16; k++) {
            float4 av = *reinterpret_cast<const float4*>(&As[k][ty*4]);
            float4 wv = *reinterpret_cast<const float4*>(&Ws[k][tx*4]);
            ull w01 = pack2(wv.x, wv.y);
            ull w23 = pack2(wv.z, wv.w);
            float aa[4] = {av.x, av.y, av.z, av.w};
            #pragma unroll
            for (int i = 0; i < 4; i++) {
                ull ap = pack2(aa[i], aa[i]);
                fma2(acc[i][0], ap, w01);
                fma2(acc[i][1], ap, w23);
            }
        }
        __syncthreads();
    }
    #pragma unroll
    for (int i = 0; i < 4; i++) {
        float4 o;
        unpack2(acc[i][0], o.x, o.y);
        unpack2(acc[i][1], o.z, o.w);
        *reinterpret_cast<float4*>(&C[(size_t)(m0+ty*4+i)*256 + n0 + tx*4]) = o;
    }
}

// ---------------------------------------------------------------------------
// Kernel 3: energy + softmax + context, per (b, 8-d tile).
// energy[b,d,e] = sum_h tanh(was[b,e,h] + uah[b,d,h]) * V[h]
// p = softmax_e(energy);  c[b,d,h] = sum_e p * ortho[b,e,h]
// 256 threads (8 warps). warp handles one e per pass (16 passes),
// accumulating 8 d's at once; next pass's was-row is register-prefetched.
// ---------------------------------------------------------------------------
__global__ void attn_kernel(const float* __restrict__ Va,
                            float* __restrict__ c_out,
                            float* __restrict__ e_out) {
    __shared__ float  u_sm[8][H];
    __shared__ float  V_sm[H];
    __shared__ float  en_sm[8][TE];
    __shared__ float2 en2_sm[4][TE];   // packed pairs (p[2k], p[2k+1]) per e

    int b   = blockIdx.x >> 4;
    int d0  = (blockIdx.x & 15) * 8;
    int tid = threadIdx.x;
    int warp = tid >> 5, lane = tid & 31;

    {   // load u_sm: 8 rows x 256 floats = 512 float4
        const float4* usrc = reinterpret_cast<const float4*>(g_uah + (size_t)(b*TD + d0)*H);
        float4* udst = reinterpret_cast<float4*>(&u_sm[0][0]);
        udst[tid]       = usrc[tid];
        udst[tid + 256] = usrc[tid + 256];
        V_sm[tid] = Va[tid];
    }
    __syncthreads();

    const float* wbase = g_was + (size_t)(b*TE)*H;

    // ---- energies, with register prefetch of next was row ----
    float w[8];
    {
        const float* wr = wbase + warp*H;
        #pragma unroll
        for (int j = 0; j < 8; j++) w[j] = wr[lane + 32*j];
    }
    #pragma unroll 1
    for (int pass = 0; pass < 16; pass++) {
        int e = pass*8 + warp;
        float wn[8];
        if (pass < 15) {
            const float* wr = wbase + (e + 8)*H;
            #pragma unroll
            for (int j = 0; j < 8; j++) wn[j] = wr[lane + 32*j];
        }
        float a0=0.f,a1=0.f,a2=0.f,a3=0.f,a4=0.f,a5=0.f,a6=0.f,a7=0.f;
        #pragma unroll
        for (int j = 0; j < 8; j++) {
            int hh = lane + 32*j;
            float wv = w[j];
            float v  = V_sm[hh];
            a0 += tanh_fast(wv + u_sm[0][hh]) * v;
            a1 += tanh_fast(wv + u_sm[1][hh]) * v;
            a2 += tanh_fast(wv + u_sm[2][hh]) * v;
            a3 += tanh_fast(wv + u_sm[3][hh]) * v;
            a4 += tanh_fast(wv + u_sm[4][hh]) * v;
            a5 += tanh_fast(wv + u_sm[5][hh]) * v;
            a6 += tanh_fast(wv + u_sm[6][hh]) * v;
            a7 += tanh_fast(wv + u_sm[7][hh]) * v;
        }
        #pragma unroll
        for (int off = 16; off; off >>= 1) {
            a0 += __shfl_xor_sync(0xffffffffu, a0, off);
            a1 += __shfl_xor_sync(0xffffffffu, a1, off);
            a2 += __shfl_xor_sync(0xffffffffu, a2, off);
            a3 += __shfl_xor_sync(0xffffffffu, a3, off);
            a4 += __shfl_xor_sync(0xffffffffu, a4, off);
            a5 += __shfl_xor_sync(0xffffffffu, a5, off);
            a6 += __shfl_xor_sync(0xffffffffu, a6, off);
            a7 += __shfl_xor_sync(0xffffffffu, a7, off);
        }
        if (lane == 0) {
            en_sm[0][e] = a0; en_sm[1][e] = a1; en_sm[2][e] = a2; en_sm[3][e] = a3;
            en_sm[4][e] = a4; en_sm[5][e] = a5; en_sm[6][e] = a6; en_sm[7][e] = a7;
        }
        #pragma unroll
        for (int j = 0; j < 8; j++) w[j] = wn[j];
    }
    __syncthreads();

    // ---- softmax over e: warp d handles row d (8 warps = 8 d's) ----
    {
        int d = warp;
        float v0 = en_sm[d][lane],      v1 = en_sm[d][lane+32];
        float v2 = en_sm[d][lane+64],   v3 = en_sm[d][lane+96];
        float m = fmaxf(fmaxf(v0, v1), fmaxf(v2, v3));
        #pragma unroll
        for (int off = 16; off; off >>= 1)
            m = fmaxf(m, __shfl_xor_sync(0xffffffffu, m, off));
        v0 = __expf(v0 - m); v1 = __expf(v1 - m);
        v2 = __expf(v2 - m); v3 = __expf(v3 - m);
        float s = v0 + v1 + v2 + v3;
        #pragma unroll
        for (int off = 16; off; off >>= 1)
            s += __shfl_xor_sync(0xffffffffu, s, off);
        float inv = 1.0f / s;
        v0 *= inv; v1 *= inv; v2 *= inv; v3 *= inv;
        float* er = e_out + (size_t)(b*TD + d0 + d)*TE;
        er[lane]    = v0; er[lane+32] = v1;
        er[lane+64] = v2; er[lane+96] = v3;
        // scatter into packed pair layout for context stage
        float* dst = reinterpret_cast<float*>(&en2_sm[d>>1][0]) + (d & 1);
        dst[2*lane]      = v0; dst[2*(lane+32)] = v1;
        dst[2*(lane+64)] = v2; dst[2*(lane+96)] = v3;
    }
    __syncthreads();

    // ---- context: c[d][h] = sum_e p[d][e] * ortho[b,e,h]  (f32x2 packed) ----
    {
        int hh = tid;
        const float* orow = g_ortho + (size_t)(b*TE)*H + hh;
        ull c01 = 0ull, c23 = 0ull, c45 = 0ull, c67 = 0ull;
        #pragma unroll 4
        for (int e = 0; e < TE; e++) {
            float x = orow[e*H];
            ull xx = pack2(x, x);
            fma2(c01, xx, *reinterpret_cast<const ull*>(&en2_sm[0][e]));
            fma2(c23, xx, *reinterpret_cast<const ull*>(&en2_sm[1][e]));
            fma2(c45, xx, *reinterpret_cast<const ull*>(&en2_sm[2][e]));
            fma2(c67, xx, *reinterpret_cast<const ull*>(&en2_sm[3][e]));
        }
        float c[8];
        unpack2(c01, c[0], c[1]); unpack2(c23, c[2], c[3]);
        unpack2(c45, c[4], c[5]); unpack2(c67, c[6], c[7]);
        #pragma unroll
        for (int d = 0; d < 8; d++)
            c_out[(size_t)(b*TD + d0 + d)*H + hh] = c[d];
    }
}

// ---------------------------------------------------------------------------
extern "C" void kernel_launch(void* const* d_in, const int* in_sizes, int n_in,
                              void* d_out, int out_size) {
    const float* enc = (const float*)d_in[0];
    const float* dec = (const float*)d_in[1];
    const float* Wa  = (const float*)d_in[2];
    const float* Ua  = (const float*)d_in[3];
    const float* Va  = (const float*)d_in[4];

    float* out   = (float*)d_out;
    float* c_out = out;                    // [B, TD, H]
    float* e_out = out + (size_t)B*TD*H;   // [B, TD, TE]

    ortho_kernel<<<32, 128>>>(enc);
    gemm_both<<<dim3(32, 4, 2), 256>>>(dec, Wa, Ua);
    attn_kernel<<<B * (TD/8), 256>>>(Va, c_out, e_out);
}